// round 1
// baseline (speedup 1.0000x reference)
#include <cuda_runtime.h>
#include <cuda_bf16.h>

// Precomputed folded weights:
//   g_v[k]   = sum_d weight_two[k,d] * weight_three[d]      (k in 0..255)
//   g_w3b[d] = weight_three[128+d]                          (d in 0..127)
__device__ float g_v[256];
__device__ float g_w3b[128];

__global__ void precompute_kernel(const float* __restrict__ W2,
                                  const float* __restrict__ W3) {
    int k = threadIdx.x;  // 256 threads
    if (k < 256) {
        float s = 0.f;
        const float* row = W2 + k * 128;
        #pragma unroll 4
        for (int d = 0; d < 128; ++d) s = fmaf(row[d], W3[d], s);
        g_v[k] = s;
    }
    if (k < 128) g_w3b[k] = W3[128 + k];
}

__global__ __launch_bounds__(256) void neumf_kernel(
    const int* __restrict__ e_true,
    const int* __restrict__ e_false,
    const float* __restrict__ z,
    float* __restrict__ out,
    int E_true, int E_total)
{
    const int lane = threadIdx.x & 31;
    const int warp = (blockIdx.x * blockDim.x + threadIdx.x) >> 5;
    const int nwarps = (gridDim.x * blockDim.x) >> 5;

    // Per-lane folded weights, loaded once (L2/L1 hit, amortized over ~100 edges)
    const float4 va = *reinterpret_cast<const float4*>(&g_v[lane * 4]);        // v[0..127]
    const float4 vb = *reinterpret_cast<const float4*>(&g_v[128 + lane * 4]);  // v[128..255]
    const float4 w  = *reinterpret_cast<const float4*>(&g_w3b[lane * 4]);

    for (int e = warp; e < E_total; e += nwarps) {
        int2 idx;
        if (lane == 0) {
            const int* p = (e < E_true) ? (e_true + 2 * e)
                                        : (e_false + 2 * (e - E_true));
            idx = *reinterpret_cast<const int2*>(p);
        }
        idx.x = __shfl_sync(0xFFFFFFFFu, idx.x, 0);
        idx.y = __shfl_sync(0xFFFFFFFFu, idx.y, 0);

        const float4 a = __ldg(reinterpret_cast<const float4*>(
            z + (size_t)idx.x * 128 + lane * 4));
        const float4 b = __ldg(reinterpret_cast<const float4*>(
            z + (size_t)idx.y * 128 + lane * 4));

        float s = 0.f;
        s = fmaf(fmaxf(a.x, 0.f), va.x, s);
        s = fmaf(fmaxf(a.y, 0.f), va.y, s);
        s = fmaf(fmaxf(a.z, 0.f), va.z, s);
        s = fmaf(fmaxf(a.w, 0.f), va.w, s);
        s = fmaf(fmaxf(b.x, 0.f), vb.x, s);
        s = fmaf(fmaxf(b.y, 0.f), vb.y, s);
        s = fmaf(fmaxf(b.z, 0.f), vb.z, s);
        s = fmaf(fmaxf(b.w, 0.f), vb.w, s);
        s = fmaf(a.x * b.x, w.x, s);
        s = fmaf(a.y * b.y, w.y, s);
        s = fmaf(a.z * b.z, w.z, s);
        s = fmaf(a.w * b.w, w.w, s);

        // Warp reduce
        #pragma unroll
        for (int off = 16; off; off >>= 1)
            s += __shfl_xor_sync(0xFFFFFFFFu, s, off);

        if (lane == 0)
            out[e] = 1.f / (1.f + __expf(-s));
    }
}

extern "C" void kernel_launch(void* const* d_in, const int* in_sizes, int n_in,
                              void* d_out, int out_size) {
    // metadata order: X, train_edges, train_false_edges, z, weight_two, weight_three
    const int*   e_true  = (const int*)  d_in[1];
    const int*   e_false = (const int*)  d_in[2];
    const float* z       = (const float*)d_in[3];
    const float* W2      = (const float*)d_in[4];
    const float* W3      = (const float*)d_in[5];
    float* out = (float*)d_out;

    const int E_true  = in_sizes[1] / 2;
    const int E_total = E_true + in_sizes[2] / 2;

    precompute_kernel<<<1, 256>>>(W2, W3);

    // Persistent-ish grid-stride: 148 SMs * 8 blocks * 256 thr = 9472 warps
    const int blocks = 148 * 8;
    neumf_kernel<<<blocks, 256>>>(e_true, e_false, z, out, E_true, E_total);
}

// round 2
// speedup vs baseline: 1.3882x; 1.3882x over previous
#include <cuda_runtime.h>
#include <cuda_bf16.h>

// Folded weights: logit(e) = sum_d relu(zi[d])*v[d] + relu(zj[d])*v[128+d]
//                          + zi[d]*zj[d]*w3b[d]
//   g_v[k]   = sum_d weight_two[k,d] * weight_three[d]
//   g_w3b[d] = weight_three[128+d]
__device__ float g_v[256];
__device__ float g_w3b[128];

__global__ void precompute_kernel(const float* __restrict__ W2,
                                  const float* __restrict__ W3) {
    int k = threadIdx.x;  // 256 threads
    if (k < 256) {
        float s = 0.f;
        const float* row = W2 + k * 128;
        #pragma unroll 4
        for (int d = 0; d < 128; ++d) s = fmaf(row[d], W3[d], s);
        g_v[k] = s;
    }
    if (k < 128) g_w3b[k] = W3[128 + k];
}

__device__ __forceinline__ float edge_partial(const float4 a, const float4 b,
                                              const float4 va, const float4 vb,
                                              const float4 w) {
    float s = 0.f;
    s = fmaf(fmaxf(a.x, 0.f), va.x, s);
    s = fmaf(fmaxf(a.y, 0.f), va.y, s);
    s = fmaf(fmaxf(a.z, 0.f), va.z, s);
    s = fmaf(fmaxf(a.w, 0.f), va.w, s);
    s = fmaf(fmaxf(b.x, 0.f), vb.x, s);
    s = fmaf(fmaxf(b.y, 0.f), vb.y, s);
    s = fmaf(fmaxf(b.z, 0.f), vb.z, s);
    s = fmaf(fmaxf(b.w, 0.f), vb.w, s);
    s = fmaf(a.x * b.x, w.x, s);
    s = fmaf(a.y * b.y, w.y, s);
    s = fmaf(a.z * b.z, w.z, s);
    s = fmaf(a.w * b.w, w.w, s);
    return s;
}

__global__ __launch_bounds__(256) void neumf_kernel(
    const int* __restrict__ e_true,
    const int* __restrict__ e_false,
    const float* __restrict__ z,
    float* __restrict__ out,
    int E_true, int E_total)
{
    const int lane   = threadIdx.x & 31;
    const int warp   = (blockIdx.x * blockDim.x + threadIdx.x) >> 5;
    const int nwarps = (gridDim.x * blockDim.x) >> 5;

    const float4 va = *reinterpret_cast<const float4*>(&g_v[lane * 4]);
    const float4 vb = *reinterpret_cast<const float4*>(&g_v[128 + lane * 4]);
    const float4 w  = *reinterpret_cast<const float4*>(&g_w3b[lane * 4]);

    const float4* __restrict__ zr = reinterpret_cast<const float4*>(z);

    // 4 edges per warp-iteration: 8 independent row-gathers in flight.
    int e = warp * 4;
    const int stride = nwarps * 4;

    for (; e + 3 < E_total; e += stride) {
        // Uniform index loads (all lanes same address -> broadcast, no SHFL)
        int2 i0, i1, i2, i3;
        {
            int k0 = e, k1 = e + 1, k2 = e + 2, k3 = e + 3;
            i0 = __ldg(reinterpret_cast<const int2*>(
                 (k0 < E_true ? e_true + 2 * k0 : e_false + 2 * (k0 - E_true))));
            i1 = __ldg(reinterpret_cast<const int2*>(
                 (k1 < E_true ? e_true + 2 * k1 : e_false + 2 * (k1 - E_true))));
            i2 = __ldg(reinterpret_cast<const int2*>(
                 (k2 < E_true ? e_true + 2 * k2 : e_false + 2 * (k2 - E_true))));
            i3 = __ldg(reinterpret_cast<const int2*>(
                 (k3 < E_true ? e_true + 2 * k3 : e_false + 2 * (k3 - E_true))));
        }

        // Issue all 8 gathers before consuming any (MLP=8)
        const float4 a0 = __ldg(zr + (size_t)i0.x * 32 + lane);
        const float4 b0 = __ldg(zr + (size_t)i0.y * 32 + lane);
        const float4 a1 = __ldg(zr + (size_t)i1.x * 32 + lane);
        const float4 b1 = __ldg(zr + (size_t)i1.y * 32 + lane);
        const float4 a2 = __ldg(zr + (size_t)i2.x * 32 + lane);
        const float4 b2 = __ldg(zr + (size_t)i2.y * 32 + lane);
        const float4 a3 = __ldg(zr + (size_t)i3.x * 32 + lane);
        const float4 b3 = __ldg(zr + (size_t)i3.y * 32 + lane);

        float s0 = edge_partial(a0, b0, va, vb, w);
        float s1 = edge_partial(a1, b1, va, vb, w);
        float s2 = edge_partial(a2, b2, va, vb, w);
        float s3 = edge_partial(a3, b3, va, vb, w);

        // 4 independent butterfly chains — latency overlaps
        #pragma unroll
        for (int off = 16; off; off >>= 1) {
            s0 += __shfl_xor_sync(0xFFFFFFFFu, s0, off);
            s1 += __shfl_xor_sync(0xFFFFFFFFu, s1, off);
            s2 += __shfl_xor_sync(0xFFFFFFFFu, s2, off);
            s3 += __shfl_xor_sync(0xFFFFFFFFu, s3, off);
        }

        if (lane == 0) {
            out[e + 0] = 1.f / (1.f + __expf(-s0));
            out[e + 1] = 1.f / (1.f + __expf(-s1));
            out[e + 2] = 1.f / (1.f + __expf(-s2));
            out[e + 3] = 1.f / (1.f + __expf(-s3));
        }
    }

    // Tail
    for (; e < E_total; ++e) {
        int2 i0 = __ldg(reinterpret_cast<const int2*>(
             (e < E_true ? e_true + 2 * e : e_false + 2 * (e - E_true))));
        const float4 a = __ldg(zr + (size_t)i0.x * 32 + lane);
        const float4 b = __ldg(zr + (size_t)i0.y * 32 + lane);
        float s = edge_partial(a, b, va, vb, w);
        #pragma unroll
        for (int off = 16; off; off >>= 1)
            s += __shfl_xor_sync(0xFFFFFFFFu, s, off);
        if (lane == 0)
            out[e] = 1.f / (1.f + __expf(-s));
    }
}

extern "C" void kernel_launch(void* const* d_in, const int* in_sizes, int n_in,
                              void* d_out, int out_size) {
    // metadata order: X, train_edges, train_false_edges, z, weight_two, weight_three
    const int*   e_true  = (const int*)  d_in[1];
    const int*   e_false = (const int*)  d_in[2];
    const float* z       = (const float*)d_in[3];
    const float* W2      = (const float*)d_in[4];
    const float* W3      = (const float*)d_in[5];
    float* out = (float*)d_out;

    const int E_true  = in_sizes[1] / 2;
    const int E_total = E_true + in_sizes[2] / 2;

    precompute_kernel<<<1, 256>>>(W2, W3);

    const int blocks = 148 * 8;
    neumf_kernel<<<blocks, 256>>>(e_true, e_false, z, out, E_true, E_total);
}

// round 3
// speedup vs baseline: 1.6657x; 1.1999x over previous
#include <cuda_runtime.h>
#include <cuda_bf16.h>

// Folded weights: logit(e) = sum_d relu(zi[d])*v[d] + relu(zj[d])*v[128+d]
//                          + zi[d]*zj[d]*w3b[d]
__device__ float g_v[256];
__device__ float g_w3b[128];

__global__ void precompute_kernel(const float* __restrict__ W2,
                                  const float* __restrict__ W3) {
    int k = threadIdx.x;  // 256 threads
    if (k < 256) {
        float s = 0.f;
        const float* row = W2 + k * 128;
        #pragma unroll 4
        for (int d = 0; d < 128; ++d) s = fmaf(row[d], W3[d], s);
        g_v[k] = s;
    }
    if (k < 128) g_w3b[k] = W3[128 + k];
}

__device__ __forceinline__ float edge_partial(const float4 a, const float4 b,
                                              const float4 va, const float4 vb,
                                              const float4 w) {
    float s = 0.f;
    s = fmaf(fmaxf(a.x, 0.f), va.x, s);
    s = fmaf(fmaxf(a.y, 0.f), va.y, s);
    s = fmaf(fmaxf(a.z, 0.f), va.z, s);
    s = fmaf(fmaxf(a.w, 0.f), va.w, s);
    s = fmaf(fmaxf(b.x, 0.f), vb.x, s);
    s = fmaf(fmaxf(b.y, 0.f), vb.y, s);
    s = fmaf(fmaxf(b.z, 0.f), vb.z, s);
    s = fmaf(fmaxf(b.w, 0.f), vb.w, s);
    s = fmaf(a.x * b.x, w.x, s);
    s = fmaf(a.y * b.y, w.y, s);
    s = fmaf(a.z * b.z, w.z, s);
    s = fmaf(a.w * b.w, w.w, s);
    return s;
}

// Reduce 4 warp-wide accumulators with 9 SHFL + 3 SEL.
// Result: lane0 -> sum(s0), lane16 -> sum(s1), lane8 -> sum(s2), lane24 -> sum(s3).
__device__ __forceinline__ float reduce4(float s0, float s1, float s2, float s3,
                                         int lane) {
    s0 += __shfl_xor_sync(0xFFFFFFFFu, s0, 16);
    s1 += __shfl_xor_sync(0xFFFFFFFFu, s1, 16);
    s2 += __shfl_xor_sync(0xFFFFFFFFu, s2, 16);
    s3 += __shfl_xor_sync(0xFFFFFFFFu, s3, 16);
    float c01 = (lane & 16) ? s1 : s0;
    float c23 = (lane & 16) ? s3 : s2;
    c01 += __shfl_xor_sync(0xFFFFFFFFu, c01, 8);
    c23 += __shfl_xor_sync(0xFFFFFFFFu, c23, 8);
    float d = (lane & 8) ? c23 : c01;
    d += __shfl_xor_sync(0xFFFFFFFFu, d, 4);
    d += __shfl_xor_sync(0xFFFFFFFFu, d, 2);
    d += __shfl_xor_sync(0xFFFFFFFFu, d, 1);
    return d;
}

__global__ __launch_bounds__(256, 2) void neumf_kernel(
    const int* __restrict__ e_true,
    const int* __restrict__ e_false,
    const float* __restrict__ z,
    float* __restrict__ out,
    int E_true, int E_total)
{
    const int lane   = threadIdx.x & 31;
    const int warp   = (blockIdx.x * blockDim.x + threadIdx.x) >> 5;
    const int nwarps = (gridDim.x * blockDim.x) >> 5;

    const float4 va = *reinterpret_cast<const float4*>(&g_v[lane * 4]);
    const float4 vb = *reinterpret_cast<const float4*>(&g_v[128 + lane * 4]);
    const float4 w  = *reinterpret_cast<const float4*>(&g_w3b[lane * 4]);

    const float4* __restrict__ zr = reinterpret_cast<const float4*>(z);

    int e = warp * 8;
    const int stride = nwarps * 8;

    for (; e + 7 < E_total; e += stride) {
        // --- indices: 4 uniform int4 loads when group doesn't straddle ---
        int2 id[8];
        if (e + 8 <= E_true) {
            const int4* p = reinterpret_cast<const int4*>(e_true + 2 * e);
            int4 q0 = __ldg(p + 0), q1 = __ldg(p + 1);
            int4 q2 = __ldg(p + 2), q3 = __ldg(p + 3);
            id[0] = make_int2(q0.x, q0.y); id[1] = make_int2(q0.z, q0.w);
            id[2] = make_int2(q1.x, q1.y); id[3] = make_int2(q1.z, q1.w);
            id[4] = make_int2(q2.x, q2.y); id[5] = make_int2(q2.z, q2.w);
            id[6] = make_int2(q3.x, q3.y); id[7] = make_int2(q3.z, q3.w);
        } else if (e >= E_true) {
            const int4* p = reinterpret_cast<const int4*>(e_false + 2 * (e - E_true));
            int4 q0 = __ldg(p + 0), q1 = __ldg(p + 1);
            int4 q2 = __ldg(p + 2), q3 = __ldg(p + 3);
            id[0] = make_int2(q0.x, q0.y); id[1] = make_int2(q0.z, q0.w);
            id[2] = make_int2(q1.x, q1.y); id[3] = make_int2(q1.z, q1.w);
            id[4] = make_int2(q2.x, q2.y); id[5] = make_int2(q2.z, q2.w);
            id[6] = make_int2(q3.x, q3.y); id[7] = make_int2(q3.z, q3.w);
        } else {
            #pragma unroll
            for (int k = 0; k < 8; ++k) {
                int ek = e + k;
                id[k] = __ldg(reinterpret_cast<const int2*>(
                    ek < E_true ? e_true + 2 * ek
                                : e_false + 2 * (ek - E_true)));
            }
        }

        // --- 16 gathers, all issued before any consume (MLP=16) ---
        float4 a[8], b[8];
        #pragma unroll
        for (int k = 0; k < 8; ++k) {
            a[k] = __ldg(zr + (((size_t)id[k].x << 5) + lane));
            b[k] = __ldg(zr + (((size_t)id[k].y << 5) + lane));
        }

        float s[8];
        #pragma unroll
        for (int k = 0; k < 8; ++k)
            s[k] = edge_partial(a[k], b[k], va, vb, w);

        float d0 = reduce4(s[0], s[1], s[2], s[3], lane);
        float d1 = reduce4(s[4], s[5], s[6], s[7], lane);

        // lanes 0,16,8,24 hold results for edges e+{0,1,2,3} (and +4..7 in d1)
        if ((lane & 7) == 0) {
            int off = ((lane >> 3) & 1) * 2 + (lane >> 4);  // 0->0, 8->2, 16->1, 24->3
            out[e + off]     = 1.f / (1.f + __expf(-d0));
            out[e + 4 + off] = 1.f / (1.f + __expf(-d1));
        }
    }

    // Tail
    for (; e < E_total; ++e) {
        int2 i0 = __ldg(reinterpret_cast<const int2*>(
             e < E_true ? e_true + 2 * e : e_false + 2 * (e - E_true)));
        const float4 aa = __ldg(zr + (((size_t)i0.x << 5) + lane));
        const float4 bb = __ldg(zr + (((size_t)i0.y << 5) + lane));
        float s = edge_partial(aa, bb, va, vb, w);
        #pragma unroll
        for (int off = 16; off; off >>= 1)
            s += __shfl_xor_sync(0xFFFFFFFFu, s, off);
        if (lane == 0)
            out[e] = 1.f / (1.f + __expf(-s));
    }
}

extern "C" void kernel_launch(void* const* d_in, const int* in_sizes, int n_in,
                              void* d_out, int out_size) {
    // metadata order: X, train_edges, train_false_edges, z, weight_two, weight_three
    const int*   e_true  = (const int*)  d_in[1];
    const int*   e_false = (const int*)  d_in[2];
    const float* z       = (const float*)d_in[3];
    const float* W2      = (const float*)d_in[4];
    const float* W3      = (const float*)d_in[5];
    float* out = (float*)d_out;

    const int E_true  = in_sizes[1] / 2;
    const int E_total = E_true + in_sizes[2] / 2;

    precompute_kernel<<<1, 256>>>(W2, W3);

    // Size grid to exact residency (persistent grid-stride; avoids wave-2 imbalance)
    int sm_count = 148, blocks_per_sm = 2;
    cudaDeviceGetAttribute(&sm_count, cudaDevAttrMultiProcessorCount, 0);
    cudaOccupancyMaxActiveBlocksPerMultiprocessor(&blocks_per_sm, neumf_kernel, 256, 0);
    if (blocks_per_sm < 1) blocks_per_sm = 1;

    neumf_kernel<<<sm_count * blocks_per_sm, 256>>>(e_true, e_false, z, out,
                                                    E_true, E_total);
}